// round 16
// baseline (speedup 1.0000x reference)
#include <cuda_runtime.h>
#include <cstdint>

// Problem constants (shapes fixed by the dataset; sizes re-derived defensively).
#define D 128
#define MAX_NODES 100000

// Scratch: y = x @ W   (51.2 MB static device array — allocation-free per rules)
__device__ float g_y[(size_t)MAX_NODES * D];

// ---------------------------------------------------------------------------
// Kernel 1: y = x @ W    (fp32 SIMT GEMM, M-tile 64, full N=128, K-chunk 32)
// block = 256 threads: tx = tid&31 -> 4 output cols (float4), ty = tid>>5 -> 8 rows
// ---------------------------------------------------------------------------
__global__ void __launch_bounds__(256) gemm_xw_kernel(
    const float* __restrict__ x, const float* __restrict__ W,
    float* __restrict__ y, int N)
{
    __shared__ float sX[64][33];   // 64 rows x 32 k, padded
    __shared__ float sW[32][128];  // 32 k x 128 cols

    const int tid  = threadIdx.x;
    const int tx   = tid & 31;      // col group (tx*4 .. tx*4+3)
    const int ty   = tid >> 5;      // row group (ty*8 .. ty*8+7)
    const int row0 = blockIdx.x * 64;

    float acc[8][4];
#pragma unroll
    for (int r = 0; r < 8; r++)
#pragma unroll
        for (int c = 0; c < 4; c++) acc[r][c] = 0.f;

    for (int k0 = 0; k0 < D; k0 += 32) {
        // Load x tile: warp w loads rows w, w+8, ..., w+56 ; lane = k-col (coalesced 128B)
#pragma unroll
        for (int i = 0; i < 8; i++) {
            int r = ty + i * 8;
            int row = row0 + r;
            float v = 0.f;
            if (row < N) v = x[(size_t)row * D + k0 + tx];
            sX[r][tx] = v;
        }
        // Load W tile: 32 k-rows x 128 cols; warp w loads k-rows w, w+8, w+16, w+24 (float4, coalesced)
#pragma unroll
        for (int i = 0; i < 4; i++) {
            int kk = ty + i * 8;
            float4 wv = *reinterpret_cast<const float4*>(&W[(size_t)(k0 + kk) * D + tx * 4]);
            *reinterpret_cast<float4*>(&sW[kk][tx * 4]) = wv;
        }
        __syncthreads();

#pragma unroll
        for (int kk = 0; kk < 32; kk++) {
            float4 wv = *reinterpret_cast<const float4*>(&sW[kk][tx * 4]);
#pragma unroll
            for (int r = 0; r < 8; r++) {
                float xa = sX[ty * 8 + r][kk];     // warp-broadcast
                acc[r][0] = fmaf(xa, wv.x, acc[r][0]);
                acc[r][1] = fmaf(xa, wv.y, acc[r][1]);
                acc[r][2] = fmaf(xa, wv.z, acc[r][2]);
                acc[r][3] = fmaf(xa, wv.w, acc[r][3]);
            }
        }
        __syncthreads();
    }

#pragma unroll
    for (int r = 0; r < 8; r++) {
        int row = row0 + ty * 8 + r;
        if (row < N) {
            float4 o = make_float4(acc[r][0], acc[r][1], acc[r][2], acc[r][3]);
            *reinterpret_cast<float4*>(&y[(size_t)row * D + tx * 4]) = o;
        }
    }
}

// ---------------------------------------------------------------------------
// Kernel 2: out[i][:] = b  (broadcast init; d_out is poisoned 0xAA before timing)
// ---------------------------------------------------------------------------
__global__ void __launch_bounds__(256) init_bias_kernel(
    float* __restrict__ out, const float* __restrict__ b, int N)
{
    const int total = N * (D / 4);                 // float4 count
    const int stride = gridDim.x * blockDim.x;
    // cache b as float4 in smem once per block
    __shared__ float4 sb[D / 4];
    if (threadIdx.x < D / 4)
        sb[threadIdx.x] = reinterpret_cast<const float4*>(b)[threadIdx.x];
    __syncthreads();

    float4* out4 = reinterpret_cast<float4*>(out);
    for (int idx = blockIdx.x * blockDim.x + threadIdx.x; idx < total; idx += stride) {
        out4[idx] = sb[idx & (D / 4 - 1)];
    }
}

// ---------------------------------------------------------------------------
// Kernel 3: scatter  out[src] += val * y[dst]
// One warp processes 32 edges: lanes cooperatively load 32 (src,dst,val) triples
// (coalesced), then for each edge the full warp moves 128 floats as float4 and
// issues red.global.add.v4.f32 (vector atomic, sm_90+).
// ---------------------------------------------------------------------------
__global__ void __launch_bounds__(256) scatter_kernel(
    const int* __restrict__ src, const int* __restrict__ dst,
    const float* __restrict__ val, const float* __restrict__ y,
    float* __restrict__ out, int E)
{
    const int warp = (blockIdx.x * blockDim.x + threadIdx.x) >> 5;
    const int lane = threadIdx.x & 31;
    const int e0 = warp * 32;
    if (e0 >= E) return;
    const int nE = min(32, E - e0);

    int   s = 0, d = 0;
    float v = 0.f;
    if (lane < nE) {
        s = src[e0 + lane];
        d = dst[e0 + lane];
        v = val[e0 + lane];
    }

    for (int i = 0; i < nE; i++) {
        const int   si = __shfl_sync(0xffffffffu, s, i);
        const int   di = __shfl_sync(0xffffffffu, d, i);
        const float vi = __shfl_sync(0xffffffffu, v, i);

        const float4 yv = *reinterpret_cast<const float4*>(y + (size_t)di * D + lane * 4);
        float* p = out + (size_t)si * D + lane * 4;
        asm volatile(
            "red.global.add.v4.f32 [%0], {%1, %2, %3, %4};"
            :: "l"(p), "f"(yv.x * vi), "f"(yv.y * vi), "f"(yv.z * vi), "f"(yv.w * vi)
            : "memory");
    }
}

// ---------------------------------------------------------------------------
// Launch
// Inputs (metadata order): x[N*128] f32, edge_src[E] i32, edge_dst[E] i32,
//                          edge_val[E] f32, W[128*128] f32, b[128] f32
// Output: [N,128] f32
// ---------------------------------------------------------------------------
extern "C" void kernel_launch(void* const* d_in, const int* in_sizes, int n_in,
                              void* d_out, int out_size)
{
    const float* x   = (const float*)d_in[0];
    const int*   esr = (const int*)  d_in[1];
    const int*   eds = (const int*)  d_in[2];
    const float* ev  = (const float*)d_in[3];
    const float* W   = (const float*)d_in[4];
    const float* b   = (const float*)d_in[5];
    float*       out = (float*)d_out;

    const int N = in_sizes[0] / D;
    const int E = in_sizes[1];

    float* y;
    cudaGetSymbolAddress((void**)&y, g_y);

    // 1) y = x @ W
    int gemm_blocks = (N + 63) / 64;
    gemm_xw_kernel<<<gemm_blocks, 256>>>(x, W, y, N);

    // 2) out = b (broadcast)
    int init_blocks = (N * (D / 4) + 255) / 256;
    if (init_blocks > 16384) init_blocks = 16384;
    init_bias_kernel<<<init_blocks, 256>>>(out, b, N);

    // 3) out[src] += val * y[dst]
    int warps = (E + 31) / 32;
    int sc_blocks = (warps * 32 + 255) / 256;
    scatter_kernel<<<sc_blocks, 256>>>(esr, eds, ev, y, out, E);
}

// round 17
// speedup vs baseline: 1.0001x; 1.0001x over previous
#include <cuda_runtime.h>
#include <cstdint>

// Problem constants (shapes fixed by the dataset; sizes re-derived defensively).
#define D 128
#define MAX_NODES 100000

// Scratch: y = x @ W   (51.2 MB static device array — allocation-free per rules)
__device__ float g_y[(size_t)MAX_NODES * D];

// ---------------------------------------------------------------------------
// Kernel 1: y = x @ W    (fp32 SIMT GEMM, M-tile 64, full N=128, K-chunk 32)
// block = 256 threads: tx = tid&31 -> 4 output cols (float4), ty = tid>>5 -> 8 rows
// ---------------------------------------------------------------------------
__global__ void __launch_bounds__(256) gemm_xw_kernel(
    const float* __restrict__ x, const float* __restrict__ W,
    float* __restrict__ y, int N)
{
    __shared__ float sX[64][33];   // 64 rows x 32 k, padded
    __shared__ float sW[32][128];  // 32 k x 128 cols

    const int tid  = threadIdx.x;
    const int tx   = tid & 31;      // col group (tx*4 .. tx*4+3)
    const int ty   = tid >> 5;      // row group (ty*8 .. ty*8+7)
    const int row0 = blockIdx.x * 64;

    float acc[8][4];
#pragma unroll
    for (int r = 0; r < 8; r++)
#pragma unroll
        for (int c = 0; c < 4; c++) acc[r][c] = 0.f;

    for (int k0 = 0; k0 < D; k0 += 32) {
        // Load x tile: warp w loads rows w, w+8, ..., w+56 ; lane = k-col (coalesced 128B)
#pragma unroll
        for (int i = 0; i < 8; i++) {
            int r = ty + i * 8;
            int row = row0 + r;
            float v = 0.f;
            if (row < N) v = x[(size_t)row * D + k0 + tx];
            sX[r][tx] = v;
        }
        // Load W tile: 32 k-rows x 128 cols; warp w loads k-rows w, w+8, w+16, w+24 (float4, coalesced)
#pragma unroll
        for (int i = 0; i < 4; i++) {
            int kk = ty + i * 8;
            float4 wv = *reinterpret_cast<const float4*>(&W[(size_t)(k0 + kk) * D + tx * 4]);
            *reinterpret_cast<float4*>(&sW[kk][tx * 4]) = wv;
        }
        __syncthreads();

#pragma unroll
        for (int kk = 0; kk < 32; kk++) {
            float4 wv = *reinterpret_cast<const float4*>(&sW[kk][tx * 4]);
#pragma unroll
            for (int r = 0; r < 8; r++) {
                float xa = sX[ty * 8 + r][kk];     // warp-broadcast
                acc[r][0] = fmaf(xa, wv.x, acc[r][0]);
                acc[r][1] = fmaf(xa, wv.y, acc[r][1]);
                acc[r][2] = fmaf(xa, wv.z, acc[r][2]);
                acc[r][3] = fmaf(xa, wv.w, acc[r][3]);
            }
        }
        __syncthreads();
    }

#pragma unroll
    for (int r = 0; r < 8; r++) {
        int row = row0 + ty * 8 + r;
        if (row < N) {
            float4 o = make_float4(acc[r][0], acc[r][1], acc[r][2], acc[r][3]);
            *reinterpret_cast<float4*>(&y[(size_t)row * D + tx * 4]) = o;
        }
    }
}

// ---------------------------------------------------------------------------
// Kernel 2: out[i][:] = b  (broadcast init; d_out is poisoned 0xAA before timing)
// ---------------------------------------------------------------------------
__global__ void __launch_bounds__(256) init_bias_kernel(
    float* __restrict__ out, const float* __restrict__ b, int N)
{
    const int total = N * (D / 4);                 // float4 count
    const int stride = gridDim.x * blockDim.x;
    // cache b as float4 in smem once per block
    __shared__ float4 sb[D / 4];
    if (threadIdx.x < D / 4)
        sb[threadIdx.x] = reinterpret_cast<const float4*>(b)[threadIdx.x];
    __syncthreads();

    float4* out4 = reinterpret_cast<float4*>(out);
    for (int idx = blockIdx.x * blockDim.x + threadIdx.x; idx < total; idx += stride) {
        out4[idx] = sb[idx & (D / 4 - 1)];
    }
}

// ---------------------------------------------------------------------------
// Kernel 3: scatter  out[src] += val * y[dst]
// One warp processes 32 edges: lanes cooperatively load 32 (src,dst,val) triples
// (coalesced), then for each edge the full warp moves 128 floats as float4 and
// issues red.global.add.v4.f32 (vector atomic, sm_90+).
// ---------------------------------------------------------------------------
__global__ void __launch_bounds__(256) scatter_kernel(
    const int* __restrict__ src, const int* __restrict__ dst,
    const float* __restrict__ val, const float* __restrict__ y,
    float* __restrict__ out, int E)
{
    const int warp = (blockIdx.x * blockDim.x + threadIdx.x) >> 5;
    const int lane = threadIdx.x & 31;
    const int e0 = warp * 32;
    if (e0 >= E) return;
    const int nE = min(32, E - e0);

    int   s = 0, d = 0;
    float v = 0.f;
    if (lane < nE) {
        s = src[e0 + lane];
        d = dst[e0 + lane];
        v = val[e0 + lane];
    }

    for (int i = 0; i < nE; i++) {
        const int   si = __shfl_sync(0xffffffffu, s, i);
        const int   di = __shfl_sync(0xffffffffu, d, i);
        const float vi = __shfl_sync(0xffffffffu, v, i);

        const float4 yv = *reinterpret_cast<const float4*>(y + (size_t)di * D + lane * 4);
        float* p = out + (size_t)si * D + lane * 4;
        asm volatile(
            "red.global.add.v4.f32 [%0], {%1, %2, %3, %4};"
            :: "l"(p), "f"(yv.x * vi), "f"(yv.y * vi), "f"(yv.z * vi), "f"(yv.w * vi)
            : "memory");
    }
}

// ---------------------------------------------------------------------------
// Launch
// Inputs (metadata order): x[N*128] f32, edge_src[E] i32, edge_dst[E] i32,
//                          edge_val[E] f32, W[128*128] f32, b[128] f32
// Output: [N,128] f32
// ---------------------------------------------------------------------------
extern "C" void kernel_launch(void* const* d_in, const int* in_sizes, int n_in,
                              void* d_out, int out_size)
{
    const float* x   = (const float*)d_in[0];
    const int*   esr = (const int*)  d_in[1];
    const int*   eds = (const int*)  d_in[2];
    const float* ev  = (const float*)d_in[3];
    const float* W   = (const float*)d_in[4];
    const float* b   = (const float*)d_in[5];
    float*       out = (float*)d_out;

    const int N = in_sizes[0] / D;
    const int E = in_sizes[1];

    float* y;
    cudaGetSymbolAddress((void**)&y, g_y);

    // 1) y = x @ W
    int gemm_blocks = (N + 63) / 64;
    gemm_xw_kernel<<<gemm_blocks, 256>>>(x, W, y, N);

    // 2) out = b (broadcast)
    int init_blocks = (N * (D / 4) + 255) / 256;
    if (init_blocks > 16384) init_blocks = 16384;
    init_bias_kernel<<<init_blocks, 256>>>(out, b, N);

    // 3) out[src] += val * y[dst]
    int warps = (E + 31) / 32;
    int sc_blocks = (warps * 32 + 255) / 256;
    scatter_kernel<<<sc_blocks, 256>>>(esr, eds, ev, y, out, E);
}